// round 1
// baseline (speedup 1.0000x reference)
#include <cuda_runtime.h>
#include <math.h>

#define KNOTS 16
#define BOUNDF 5.0f
#define XD 6
#define CD 4
#define HID 128
#define SPL 47      // 3*KNOTS-1
#define LOW 3
#define OUTD 141    // LOW*SPL
#define OUTP 144    // padded to multiple of 9*16
#define TM 64
#define NTH 256
#define H1S 132     // h1/h2 row stride (132 mod 32 = 4 -> conflict-free row access)
#define PS 147      // p row stride

// shared layout (floats)
#define OFF_XS   0
#define OFF_CS   (OFF_XS + TM*XD)        // 384
#define OFF_LD   (OFF_CS + TM*CD)        // 640
#define OFF_BSH  (OFF_LD + TM*LOW)       // 832
#define OFF_WS   (OFF_BSH + OUTP)        // 976  (16B aligned)
#define OFF_H1   (OFF_WS + HID*OUTP)     // 19408
#define OFF_H2   (OFF_H1 + TM*H1S)       // 27856
#define OFF_P    (OFF_H2 + TM*H1S)       // 36304
#define SMEM_FLOATS (OFF_P + TM*PS)      // 45712
#define SMEM_BYTES (SMEM_FLOATS * 4)     // 182848

__device__ __forceinline__ float softplus_f(float v) {
    // stable: max(v,0) + log1p(exp(-|v|))
    return fmaxf(v, 0.0f) + log1pf(expf(-fabsf(v)));
}

__global__ __launch_bounds__(NTH, 1)
void nsc_kernel(const float* __restrict__ x, const float* __restrict__ c,
                const float* __restrict__ W1, const float* __restrict__ b1,
                const float* __restrict__ W2, const float* __restrict__ b2,
                const float* __restrict__ W3, const float* __restrict__ b3,
                float* __restrict__ y_out, float* __restrict__ ld_out, int N)
{
    extern __shared__ float sm[];
    float* xs  = sm + OFF_XS;
    float* cs  = sm + OFF_CS;
    float* ldsh= sm + OFF_LD;
    float* bsh = sm + OFF_BSH;
    float* ws  = sm + OFF_WS;
    float* h1s = sm + OFF_H1;
    float* h2s = sm + OFF_H2;
    float* ps  = sm + OFF_P;

    const int tid  = threadIdx.x;
    const int base = blockIdx.x * TM;
    const int nrows = min(TM, N - base);

    // ---- load inputs (zero-pad tail rows) + W1/b1 ----
    for (int i = tid; i < TM*XD; i += NTH) {
        int r = i / XD;
        xs[i] = (r < nrows) ? x[(size_t)(base + r)*XD + (i - r*XD)] : 0.0f;
    }
    for (int i = tid; i < TM*CD; i += NTH) {
        int r = i / CD;
        cs[i] = (r < nrows) ? c[(size_t)(base + r)*CD + (i - r*CD)] : 0.0f;
    }
    for (int i = tid; i < 7*HID; i += NTH) ws[i] = W1[i];
    for (int i = tid; i < HID; i += NTH)   bsh[i] = b1[i];
    __syncthreads();

    // ---- phase 1: h1 = relu([upper, c] @ W1 + b1) ----
    for (int o = tid; o < TM*HID; o += NTH) {
        int r = o >> 7, j = o & (HID-1);
        const float* hx = &xs[r*XD + LOW];
        const float* hc = &cs[r*CD];
        float acc = bsh[j];
        acc = fmaf(hx[0], ws[0*HID+j], acc);
        acc = fmaf(hx[1], ws[1*HID+j], acc);
        acc = fmaf(hx[2], ws[2*HID+j], acc);
        acc = fmaf(hc[0], ws[3*HID+j], acc);
        acc = fmaf(hc[1], ws[4*HID+j], acc);
        acc = fmaf(hc[2], ws[5*HID+j], acc);
        acc = fmaf(hc[3], ws[6*HID+j], acc);
        h1s[r*H1S + j] = fmaxf(acc, 0.0f);
    }
    __syncthreads();

    // ---- load W2 (128x128) + b2 ----
    {
        const float4* src = (const float4*)W2;
        float4* dst = (float4*)ws;
        for (int i = tid; i < HID*HID/4; i += NTH) dst[i] = src[i];
    }
    for (int i = tid; i < HID; i += NTH) bsh[i] = b2[i];
    __syncthreads();

    // ---- phase 2: h2 = relu(h1 @ W2 + b2); tile 4 rows x 8 cols / thread ----
    {
        const int cg = tid & 15, rg = tid >> 4;
        float acc[4][8];
        #pragma unroll
        for (int i = 0; i < 4; i++)
            #pragma unroll
            for (int j = 0; j < 8; j++) acc[i][j] = bsh[cg*8 + j];

        const float* h1p = &h1s[(rg*4)*H1S];
        #pragma unroll 4
        for (int k = 0; k < HID; k++) {
            float a0 = h1p[0*H1S + k];
            float a1 = h1p[1*H1S + k];
            float a2 = h1p[2*H1S + k];
            float a3 = h1p[3*H1S + k];
            float4 wa = *(const float4*)&ws[k*HID + cg*8];
            float4 wb = *(const float4*)&ws[k*HID + cg*8 + 4];
            float wv[8] = {wa.x, wa.y, wa.z, wa.w, wb.x, wb.y, wb.z, wb.w};
            #pragma unroll
            for (int j = 0; j < 8; j++) {
                acc[0][j] = fmaf(a0, wv[j], acc[0][j]);
                acc[1][j] = fmaf(a1, wv[j], acc[1][j]);
                acc[2][j] = fmaf(a2, wv[j], acc[2][j]);
                acc[3][j] = fmaf(a3, wv[j], acc[3][j]);
            }
        }
        #pragma unroll
        for (int i = 0; i < 4; i++)
            #pragma unroll
            for (int j = 0; j < 8; j++)
                h2s[(rg*4 + i)*H1S + cg*8 + j] = fmaxf(acc[i][j], 0.0f);
    }
    __syncthreads();

    // ---- load W3 (128x141 -> padded 128x144) + b3 ----
    for (int i = tid; i < HID*OUTP; i += NTH) {
        int k = i / OUTP, j = i - k*OUTP;
        ws[i] = (j < OUTD) ? W3[k*OUTD + j] : 0.0f;
    }
    for (int i = tid; i < OUTP; i += NTH) bsh[i] = (i < OUTD) ? b3[i] : 0.0f;
    __syncthreads();

    // ---- phase 3: p = h2 @ W3 + b3; tile 4 rows x 9 cols / thread ----
    {
        const int cg = tid & 15, rg = tid >> 4;
        float acc[4][9];
        #pragma unroll
        for (int i = 0; i < 4; i++)
            #pragma unroll
            for (int j = 0; j < 9; j++) acc[i][j] = bsh[cg*9 + j];

        const float* h2p = &h2s[(rg*4)*H1S];
        #pragma unroll 2
        for (int k = 0; k < HID; k++) {
            float a0 = h2p[0*H1S + k];
            float a1 = h2p[1*H1S + k];
            float a2 = h2p[2*H1S + k];
            float a3 = h2p[3*H1S + k];
            const float* wr = &ws[k*OUTP + cg*9];
            #pragma unroll
            for (int j = 0; j < 9; j++) {
                float wv = wr[j];
                acc[0][j] = fmaf(a0, wv, acc[0][j]);
                acc[1][j] = fmaf(a1, wv, acc[1][j]);
                acc[2][j] = fmaf(a2, wv, acc[2][j]);
                acc[3][j] = fmaf(a3, wv, acc[3][j]);
            }
        }
        #pragma unroll
        for (int i = 0; i < 4; i++)
            #pragma unroll
            for (int j = 0; j < 9; j++)
                ps[(rg*4 + i)*PS + cg*9 + j] = acc[i][j];
    }
    __syncthreads();

    // ---- epilogue: RQS spline per (row, d); tid = d*64 + r ----
    if (tid < TM*LOW) {
        const int r = tid & 63, d = tid >> 6;
        const float* p = &ps[r*PS + d*SPL];

        float lw[KNOTS], lh[KNOTS];
        float mw = -1e30f, mh = -1e30f;
        #pragma unroll
        for (int i = 0; i < KNOTS; i++) {
            lw[i] = p[i];         mw = fmaxf(mw, lw[i]);
            lh[i] = p[KNOTS + i]; mh = fmaxf(mh, lh[i]);
        }
        float sw = 0.0f, sh = 0.0f;
        #pragma unroll
        for (int i = 0; i < KNOTS; i++) {
            lw[i] = expf(lw[i] - mw); sw += lw[i];
            lh[i] = expf(lh[i] - mh); sh += lh[i];
        }
        const float iw = (2.0f*BOUNDF) / sw, ih = (2.0f*BOUNDF) / sh;
        #pragma unroll
        for (int i = 0; i < KNOTS; i++) { lw[i] *= iw; lh[i] *= ih; }

        const float xv = xs[r*XD + d];
        const bool oob = (xv <= -BOUNDF) || (xv >= BOUNDF);
        const float xm = oob ? -BOUNDF : xv;

        // bin search via cumsum walk (matches reference cumsum + >= count)
        float cumx = -BOUNDF, cumy = -BOUNDF;
        float xkb = 0.0f, ykb = 0.0f, wk = 1.0f, hk = 1.0f;
        int idx = 0; bool found = false;
        #pragma unroll
        for (int i = 0; i < KNOTS; i++) {
            float nx = cumx + lw[i];
            if (!found && (xm < nx || i == KNOTS-1)) {
                found = true; idx = i; xkb = cumx; ykb = cumy; wk = lw[i]; hk = lh[i];
            }
            cumx = nx; cumy += lh[i];
        }

        const float db = (idx == 0)        ? 1.0f : softplus_f(p[2*KNOTS + idx - 1]);
        const float d1 = (idx == KNOTS-1)  ? 1.0f : softplus_f(p[2*KNOTS + idx]);

        const float sk   = hk / wk;
        float relx = (xm - xkb) / wk;
        relx = fminf(fmaxf(relx, 0.0f), 1.0f);
        const float omr  = 1.0f - relx;
        const float r1   = relx * omr;
        const float den  = sk + (d1 + db - 2.0f*sk) * r1;
        const float num  = hk * (sk*relx*relx + db*r1);
        float yv = ykb + num / den;
        float ld = 2.0f*logf(sk)
                 + logf(d1*relx*relx + 2.0f*sk*r1 + db*omr*omr)
                 - 2.0f*logf(den);
        if (oob) { yv = xv; ld = 0.0f; }

        ldsh[tid] = ld;
        if (r < nrows)
            y_out[(size_t)(base + r)*XD + d] = yv;
    }
    __syncthreads();

    // ---- finalize: copy-through upper dims, sum log_det ----
    if (tid < TM && tid < nrows) {
        const int r = tid;
        const size_t g = base + r;
        y_out[g*XD + 3] = xs[r*XD + 3];
        y_out[g*XD + 4] = xs[r*XD + 4];
        y_out[g*XD + 5] = xs[r*XD + 5];
        ld_out[g] = ldsh[r] + ldsh[64 + r] + ldsh[128 + r];
    }
}

extern "C" void kernel_launch(void* const* d_in, const int* in_sizes, int n_in,
                              void* d_out, int out_size) {
    const float* x  = (const float*)d_in[0];
    const float* c  = (const float*)d_in[1];
    const float* W1 = (const float*)d_in[2];
    const float* b1 = (const float*)d_in[3];
    const float* W2 = (const float*)d_in[4];
    const float* b2 = (const float*)d_in[5];
    const float* W3 = (const float*)d_in[6];
    const float* b3 = (const float*)d_in[7];

    const int N = in_sizes[0] / XD;
    float* y    = (float*)d_out;
    float* ldet = y + (size_t)N * XD;

    cudaFuncSetAttribute(nsc_kernel, cudaFuncAttributeMaxDynamicSharedMemorySize, SMEM_BYTES);

    const int grid = (N + TM - 1) / TM;
    nsc_kernel<<<grid, NTH, SMEM_BYTES>>>(x, c, W1, b1, W2, b2, W3, b3, y, ldet, N);
}

// round 3
// speedup vs baseline: 1.0981x; 1.0981x over previous
#include <cuda_runtime.h>
#include <math.h>

#define KNOTS 16
#define BOUNDF 5.0f
#define XD 6
#define CD 4
#define HID 128
#define SPL 47      // 3*KNOTS-1
#define LOW 3
#define OUTD 141    // LOW*SPL
#define OUTP 144    // padded
#define TM 64
#define NTH 256
#define S1 66       // transposed activation stride (even -> float2 aligned, conflict-free)
#define PS 147      // p row stride (147%32=19, odd -> conflict-free column reads)

// shared layout (floats)
#define OFF_XS   0
#define OFF_CS   (OFF_XS + TM*XD)          // 384
#define OFF_LD   (OFF_CS + TM*CD)          // 640
#define OFF_BSH  (OFF_LD + TM*LOW)         // 832
#define OFF_WS   (OFF_BSH + OUTP)          // 976  (x4B = 3904, 16B aligned)
#define OFF_H1   (OFF_WS + HID*OUTP)       // 19408
#define OFF_H2   (OFF_H1 + HID*S1)         // 27856
#define OFF_P    (OFF_H2 + HID*S1)         // 36304
#define OFF_Y    (OFF_P + TM*PS)           // 45712
#define SMEM_FLOATS (OFF_Y + TM*XD)        // 46096
#define SMEM_BYTES (SMEM_FLOATS * 4)       // 184384

__device__ __forceinline__ float softplus_f(float v) {
    return fmaxf(v, 0.0f) + log1pf(expf(-fabsf(v)));
}

__global__ __launch_bounds__(NTH, 1)
void nsc_kernel(const float* __restrict__ x, const float* __restrict__ c,
                const float* __restrict__ W1, const float* __restrict__ b1,
                const float* __restrict__ W2, const float* __restrict__ b2,
                const float* __restrict__ W3, const float* __restrict__ b3,
                float* __restrict__ y_out, float* __restrict__ ld_out, int N)
{
    extern __shared__ float sm[];
    float* xs  = sm + OFF_XS;
    float* cs  = sm + OFF_CS;
    float* ldsh= sm + OFF_LD;
    float* bsh = sm + OFF_BSH;
    float* ws  = sm + OFF_WS;
    float* h1t = sm + OFF_H1;   // [k][row] transposed
    float* h2t = sm + OFF_H2;   // [k][row] transposed
    float* ps  = sm + OFF_P;    // [row][141+pad] row-major
    float* ysh = sm + OFF_Y;    // [row][6]

    const int tid  = threadIdx.x;
    const int base = blockIdx.x * TM;
    const int nrows = min(TM, N - base);

    const int w = tid >> 5, l = tid & 31;

    // ---- load inputs (zero-pad tail rows) + W1/b1 ----
    for (int i = tid; i < TM*XD; i += NTH) {
        int r = i / XD;
        xs[i] = (r < nrows) ? x[(size_t)(base + r)*XD + (i - r*XD)] : 0.0f;
    }
    for (int i = tid; i < TM*CD; i += NTH) {
        int r = i / CD;
        cs[i] = (r < nrows) ? c[(size_t)(base + r)*CD + (i - r*CD)] : 0.0f;
    }
    for (int i = tid; i < 7*HID; i += NTH) ws[i] = W1[i];
    for (int i = tid; i < HID; i += NTH)   bsh[i] = b1[i];
    __syncthreads();

    // ---- phase 1: h1t[j][r] = relu([upper, c] @ W1 + b1) ----
    for (int o = tid; o < TM*HID; o += NTH) {
        const int r = o & 63, j = o >> 6;     // per-warp: fixed j -> broadcast weight reads
        float acc = bsh[j];
        acc = fmaf(xs[r*XD+3], ws[0*HID+j], acc);
        acc = fmaf(xs[r*XD+4], ws[1*HID+j], acc);
        acc = fmaf(xs[r*XD+5], ws[2*HID+j], acc);
        acc = fmaf(cs[r*CD+0], ws[3*HID+j], acc);
        acc = fmaf(cs[r*CD+1], ws[4*HID+j], acc);
        acc = fmaf(cs[r*CD+2], ws[5*HID+j], acc);
        acc = fmaf(cs[r*CD+3], ws[6*HID+j], acc);
        h1t[j*S1 + r] = fmaxf(acc, 0.0f);     // consecutive r per warp -> conflict-free
    }
    __syncthreads();

    // ---- load W2 (128x128) + b2 ----
    {
        const float4* src = (const float4*)W2;
        float4* dst = (float4*)ws;
        for (int i = tid; i < HID*HID/4; i += NTH) dst[i] = src[i];
    }
    for (int i = tid; i < HID; i += NTH) bsh[i] = b2[i];
    __syncthreads();

    // ---- phase 2: h2 = relu(h1 @ W2 + b2) ----
    // warp w -> cols [16w, 16w+16); lane l -> rows 2l, 2l+1
    {
        const int col0 = w * 16;
        float acc0[16], acc1[16];
        #pragma unroll
        for (int j = 0; j < 16; j++) { acc0[j] = bsh[col0 + j]; acc1[j] = acc0[j]; }

        #pragma unroll 4
        for (int k = 0; k < HID; k++) {
            const float2 a = *(const float2*)&h1t[k*S1 + 2*l];
            const float4* wr = (const float4*)&ws[k*HID + col0];   // broadcast
            const float4 w0 = wr[0], w1 = wr[1], w2r = wr[2], w3r = wr[3];
            const float wv[16] = {w0.x,w0.y,w0.z,w0.w, w1.x,w1.y,w1.z,w1.w,
                                  w2r.x,w2r.y,w2r.z,w2r.w, w3r.x,w3r.y,w3r.z,w3r.w};
            #pragma unroll
            for (int j = 0; j < 16; j++) {
                acc0[j] = fmaf(a.x, wv[j], acc0[j]);
                acc1[j] = fmaf(a.y, wv[j], acc1[j]);
            }
        }
        #pragma unroll
        for (int j = 0; j < 16; j++) {
            float2 v;
            v.x = fmaxf(acc0[j], 0.0f);
            v.y = fmaxf(acc1[j], 0.0f);
            *(float2*)&h2t[(col0 + j)*S1 + 2*l] = v;   // transposed store, conflict-free
        }
    }
    __syncthreads();

    // ---- load W3 (128x141 -> padded 128x144) + b3 ----
    for (int i = tid; i < HID*OUTP; i += NTH) {
        int k = i / OUTP, j = i - k*OUTP;
        ws[i] = (j < OUTD) ? W3[k*OUTD + j] : 0.0f;
    }
    for (int i = tid; i < OUTP; i += NTH) bsh[i] = (i < OUTD) ? b3[i] : 0.0f;
    __syncthreads();

    // ---- phase 3: p = h2 @ W3 + b3 ----
    // warp w -> cols [18w, 18w+18); lane l -> rows 2l, 2l+1
    {
        const int col0 = w * 18;
        float acc0[18], acc1[18];
        #pragma unroll
        for (int j = 0; j < 18; j++) { acc0[j] = bsh[col0 + j]; acc1[j] = acc0[j]; }

        #pragma unroll 2
        for (int k = 0; k < HID; k++) {
            const float2 a = *(const float2*)&h2t[k*S1 + 2*l];
            const float* wr = &ws[k*OUTP + col0];                  // broadcast
            #pragma unroll
            for (int j = 0; j < 9; j++) {
                const float2 wp = *(const float2*)&wr[2*j];
                acc0[2*j]   = fmaf(a.x, wp.x, acc0[2*j]);
                acc1[2*j]   = fmaf(a.y, wp.x, acc1[2*j]);
                acc0[2*j+1] = fmaf(a.x, wp.y, acc0[2*j+1]);
                acc1[2*j+1] = fmaf(a.y, wp.y, acc1[2*j+1]);
            }
        }
        const int r0 = 2*l, r1 = 2*l + 1;
        #pragma unroll
        for (int j = 0; j < 18; j++) {
            ps[r0*PS + col0 + j] = acc0[j];
            ps[r1*PS + col0 + j] = acc1[j];
        }
    }
    __syncthreads();

    // ---- epilogue: RQS spline per (row, d); tid = d*64 + r ----
    if (tid < TM*LOW) {
        const int r = tid & 63, d = tid >> 6;
        const float* p = &ps[r*PS + d*SPL];

        float lw[KNOTS], lh[KNOTS];
        float mw = -1e30f, mh = -1e30f;
        #pragma unroll
        for (int i = 0; i < KNOTS; i++) {
            lw[i] = p[i];         mw = fmaxf(mw, lw[i]);
            lh[i] = p[KNOTS + i]; mh = fmaxf(mh, lh[i]);
        }
        float sw = 0.0f, sh = 0.0f;
        #pragma unroll
        for (int i = 0; i < KNOTS; i++) {
            lw[i] = expf(lw[i] - mw); sw += lw[i];
            lh[i] = expf(lh[i] - mh); sh += lh[i];
        }
        const float iw = (2.0f*BOUNDF) / sw, ih = (2.0f*BOUNDF) / sh;
        #pragma unroll
        for (int i = 0; i < KNOTS; i++) { lw[i] *= iw; lh[i] *= ih; }

        const float xv = xs[r*XD + d];
        const bool oob = (xv <= -BOUNDF) || (xv >= BOUNDF);
        const float xm = oob ? -BOUNDF : xv;

        float cumx = -BOUNDF, cumy = -BOUNDF;
        float xkb = 0.0f, ykb = 0.0f, wk = 1.0f, hk = 1.0f;
        int idx = 0; bool found = false;
        #pragma unroll
        for (int i = 0; i < KNOTS; i++) {
            float nx = cumx + lw[i];
            if (!found && (xm < nx || i == KNOTS-1)) {
                found = true; idx = i; xkb = cumx; ykb = cumy; wk = lw[i]; hk = lh[i];
            }
            cumx = nx; cumy += lh[i];
        }

        const float db = (idx == 0)        ? 1.0f : softplus_f(p[2*KNOTS + idx - 1]);
        const float d1 = (idx == KNOTS-1)  ? 1.0f : softplus_f(p[2*KNOTS + idx]);

        const float sk   = hk / wk;
        float relx = (xm - xkb) / wk;
        relx = fminf(fmaxf(relx, 0.0f), 1.0f);
        const float omr  = 1.0f - relx;
        const float r1v  = relx * omr;
        const float den  = sk + (d1 + db - 2.0f*sk) * r1v;
        const float num  = hk * (sk*relx*relx + db*r1v);
        float yv = ykb + num / den;
        float ld = 2.0f*logf(sk)
                 + logf(d1*relx*relx + 2.0f*sk*r1v + db*omr*omr)
                 - 2.0f*logf(den);
        if (oob) { yv = xv; ld = 0.0f; }

        ldsh[tid] = ld;
        ysh[r*XD + d] = yv;
    } else {
        // threads 192..255 copy through the upper dims for rows 0..63
        const int r = tid - 192;
        ysh[r*XD + 3] = xs[r*XD + 3];
        ysh[r*XD + 4] = xs[r*XD + 4];
        ysh[r*XD + 5] = xs[r*XD + 5];
    }
    __syncthreads();

    // ---- coalesced output ----
    for (int i = tid; i < nrows*XD; i += NTH)
        y_out[(size_t)base*XD + i] = ysh[i];
    if (tid < nrows)
        ld_out[base + tid] = ldsh[tid] + ldsh[64 + tid] + ldsh[128 + tid];
}

extern "C" void kernel_launch(void* const* d_in, const int* in_sizes, int n_in,
                              void* d_out, int out_size) {
    const float* x  = (const float*)d_in[0];
    const float* c  = (const float*)d_in[1];
    const float* W1 = (const float*)d_in[2];
    const float* b1 = (const float*)d_in[3];
    const float* W2 = (const float*)d_in[4];
    const float* b2 = (const float*)d_in[5];
    const float* W3 = (const float*)d_in[6];
    const float* b3 = (const float*)d_in[7];

    const int N = in_sizes[0] / XD;
    float* y    = (float*)d_out;
    float* ldet = y + (size_t)N * XD;

    cudaFuncSetAttribute(nsc_kernel, cudaFuncAttributeMaxDynamicSharedMemorySize, SMEM_BYTES);

    const int grid = (N + TM - 1) / TM;
    nsc_kernel<<<grid, NTH, SMEM_BYTES>>>(x, c, W1, b1, W2, b2, W3, b3, y, ldet, N);
}

// round 4
// speedup vs baseline: 1.2892x; 1.1741x over previous
#include <cuda_runtime.h>
#include <math.h>

#define KNOTS 16
#define BOUNDF 5.0f
#define XD 6
#define CD 4
#define HID 128
#define SPL 47      // 3*KNOTS-1
#define LOW 3
#define OUTD 141    // LOW*SPL
#define OUTP 160    // padded so each of 16 warps owns 10 cols (even -> 8B-aligned pairs)
#define TM 64
#define NTH 512
#define S1 66       // transposed stride (even -> 8B-aligned float2, conflict-free)

// shared layout (floats)
#define OFF_XS   0
#define OFF_CS   (OFF_XS + TM*XD)          // 384
#define OFF_LD   (OFF_CS + TM*CD)          // 640
#define OFF_BSH  (OFF_LD + TM*LOW)         // 832
#define OFF_WS   (OFF_BSH + OUTP)          // 992   (x4 = 3968, 16B aligned)
#define OFF_PT   (OFF_WS + HID*OUTP)       // 21472 (pt 160x66; h1t aliases first 128x66)
#define OFF_H1   OFF_PT
#define OFF_H2   (OFF_PT + OUTP*S1)        // 32032 (x4 = 128128, 16B aligned)
#define OFF_Y    (OFF_H2 + HID*S1)         // 40480
#define SMEM_FLOATS (OFF_Y + TM*XD)        // 40864
#define SMEM_BYTES (SMEM_FLOATS * 4)       // 163456

typedef unsigned long long u64;

#define FMA2(d, a, b, c) \
    asm("fma.rn.f32x2 %0, %1, %2, %3;" : "=l"(d) : "l"(a), "l"(b), "l"(c))

__device__ __forceinline__ u64 pack2(float x, float y) {
    u64 r; asm("mov.b64 %0, {%1, %2};" : "=l"(r) : "f"(x), "f"(y)); return r;
}
__device__ __forceinline__ float2 unpack2(u64 v) {
    float2 f; asm("mov.b64 {%0, %1}, %2;" : "=f"(f.x), "=f"(f.y) : "l"(v)); return f;
}

__device__ __forceinline__ float softplus_f(float v) {
    return fmaxf(v, 0.0f) + log1pf(expf(-fabsf(v)));
}

__global__ __launch_bounds__(NTH, 1)
void nsc_kernel(const float* __restrict__ x, const float* __restrict__ c,
                const float* __restrict__ W1, const float* __restrict__ b1,
                const float* __restrict__ W2, const float* __restrict__ b2,
                const float* __restrict__ W3, const float* __restrict__ b3,
                float* __restrict__ y_out, float* __restrict__ ld_out, int N)
{
    extern __shared__ float sm[];
    float* xs  = sm + OFF_XS;
    float* cs  = sm + OFF_CS;
    float* ldsh= sm + OFF_LD;
    float* bsh = sm + OFF_BSH;
    float* ws  = sm + OFF_WS;
    float* h1t = sm + OFF_H1;   // [k][row] transposed (dead after phase 2)
    float* h2t = sm + OFF_H2;   // [k][row] transposed
    float* pt  = sm + OFF_PT;   // [col][row] transposed (aliases h1t)
    float* ysh = sm + OFF_Y;    // [row][6]

    const int tid  = threadIdx.x;
    const int base = blockIdx.x * TM;
    const int nrows = min(TM, N - base);

    const int w = tid >> 5, l = tid & 31;

    // ---- load inputs (zero-pad tail rows) + W1/b1 ----
    for (int i = tid; i < TM*XD; i += NTH) {
        int r = i / XD;
        xs[i] = (r < nrows) ? x[(size_t)(base + r)*XD + (i - r*XD)] : 0.0f;
    }
    for (int i = tid; i < TM*CD; i += NTH) {
        int r = i / CD;
        cs[i] = (r < nrows) ? c[(size_t)(base + r)*CD + (i - r*CD)] : 0.0f;
    }
    for (int i = tid; i < 7*HID; i += NTH) ws[i] = W1[i];
    for (int i = tid; i < HID; i += NTH)   bsh[i] = b1[i];
    __syncthreads();

    // ---- phase 1: h1t[j][r] = relu([upper, c] @ W1 + b1) ----
    for (int o = tid; o < TM*HID; o += NTH) {
        const int r = o & 63, j = o >> 6;   // j warp-uniform -> broadcast weight reads
        float acc = bsh[j];
        acc = fmaf(xs[r*XD+3], ws[0*HID+j], acc);
        acc = fmaf(xs[r*XD+4], ws[1*HID+j], acc);
        acc = fmaf(xs[r*XD+5], ws[2*HID+j], acc);
        acc = fmaf(cs[r*CD+0], ws[3*HID+j], acc);
        acc = fmaf(cs[r*CD+1], ws[4*HID+j], acc);
        acc = fmaf(cs[r*CD+2], ws[5*HID+j], acc);
        acc = fmaf(cs[r*CD+3], ws[6*HID+j], acc);
        h1t[j*S1 + r] = fmaxf(acc, 0.0f);
    }
    __syncthreads();

    // ---- load W2 (128x128) + b2 ----
    {
        const float4* src = (const float4*)W2;
        float4* dst = (float4*)ws;
        for (int i = tid; i < HID*HID/4; i += NTH) dst[i] = src[i];
    }
    for (int i = tid; i < HID; i += NTH) bsh[i] = b2[i];
    __syncthreads();

    // ---- phase 2: h2 = relu(h1 @ W2 + b2), FFMA2 packed over column pairs ----
    // 16 warps: warp w -> cols [8w, 8w+8); lane l -> rows 2l, 2l+1
    {
        const int c0 = w * 8;
        u64 accA[4], accB[4];   // A: row 2l, B: row 2l+1; pair = cols (2p, 2p+1)
        #pragma unroll
        for (int p = 0; p < 4; p++) {
            u64 bp = *(const u64*)&bsh[c0 + 2*p];
            accA[p] = bp; accB[p] = bp;
        }
        #pragma unroll 4
        for (int k = 0; k < HID; k++) {
            const float2 a = *(const float2*)&h1t[k*S1 + 2*l];
            const u64 axx = pack2(a.x, a.x);
            const u64 ayy = pack2(a.y, a.y);
            const ulonglong2 w01 = *(const ulonglong2*)&ws[k*HID + c0];
            const ulonglong2 w23 = *(const ulonglong2*)&ws[k*HID + c0 + 4];
            FMA2(accA[0], axx, w01.x, accA[0]); FMA2(accB[0], ayy, w01.x, accB[0]);
            FMA2(accA[1], axx, w01.y, accA[1]); FMA2(accB[1], ayy, w01.y, accB[1]);
            FMA2(accA[2], axx, w23.x, accA[2]); FMA2(accB[2], ayy, w23.x, accB[2]);
            FMA2(accA[3], axx, w23.y, accA[3]); FMA2(accB[3], ayy, w23.y, accB[3]);
        }
        #pragma unroll
        for (int p = 0; p < 4; p++) {
            float2 va = unpack2(accA[p]);   // cols (c0+2p, c0+2p+1), row 2l
            float2 vb = unpack2(accB[p]);   // same cols, row 2l+1
            va.x = fmaxf(va.x, 0.0f); va.y = fmaxf(va.y, 0.0f);
            vb.x = fmaxf(vb.x, 0.0f); vb.y = fmaxf(vb.y, 0.0f);
            *(u64*)&h2t[(c0 + 2*p    )*S1 + 2*l] = pack2(va.x, vb.x);
            *(u64*)&h2t[(c0 + 2*p + 1)*S1 + 2*l] = pack2(va.y, vb.y);
        }
    }
    __syncthreads();

    // ---- load W3 (128x141 -> padded 128x160) + b3 ----
    for (int i = tid; i < HID*OUTP; i += NTH) {
        int k = i / OUTP, j = i - k*OUTP;
        ws[i] = (j < OUTD) ? W3[k*OUTD + j] : 0.0f;
    }
    for (int i = tid; i < OUTP; i += NTH) bsh[i] = (i < OUTD) ? b3[i] : 0.0f;
    __syncthreads();

    // ---- phase 3: p = h2 @ W3 + b3, FFMA2; output transposed pt[col][row] ----
    // 16 warps: warp w -> cols [10w, 10w+10); lane l -> rows 2l, 2l+1
    {
        const int c0 = w * 10;
        u64 accA[5], accB[5];
        #pragma unroll
        for (int p = 0; p < 5; p++) {
            u64 bp = *(const u64*)&bsh[c0 + 2*p];
            accA[p] = bp; accB[p] = bp;
        }
        #pragma unroll 2
        for (int k = 0; k < HID; k++) {
            const float2 a = *(const float2*)&h2t[k*S1 + 2*l];
            const u64 axx = pack2(a.x, a.x);
            const u64 ayy = pack2(a.y, a.y);
            const float* wr = &ws[k*OUTP + c0];
            #pragma unroll
            for (int p = 0; p < 5; p++) {
                const u64 wp = *(const u64*)&wr[2*p];
                FMA2(accA[p], axx, wp, accA[p]);
                FMA2(accB[p], ayy, wp, accB[p]);
            }
        }
        #pragma unroll
        for (int p = 0; p < 5; p++) {
            float2 va = unpack2(accA[p]);
            float2 vb = unpack2(accB[p]);
            *(u64*)&pt[(c0 + 2*p    )*S1 + 2*l] = pack2(va.x, vb.x);
            *(u64*)&pt[(c0 + 2*p + 1)*S1 + 2*l] = pack2(va.y, vb.y);
        }
    }
    __syncthreads();

    // ---- epilogue: RQS spline per (row, d); tid = d*64 + r ----
    if (tid < TM*LOW) {
        const int r = tid & 63, d = tid >> 6;
        const float* p = &pt[(d*SPL)*S1 + r];   // param i at p[i*S1]

        float lw[KNOTS], lh[KNOTS];
        float mw = -1e30f, mh = -1e30f;
        #pragma unroll
        for (int i = 0; i < KNOTS; i++) {
            lw[i] = p[i*S1];           mw = fmaxf(mw, lw[i]);
            lh[i] = p[(KNOTS+i)*S1];   mh = fmaxf(mh, lh[i]);
        }
        float sw = 0.0f, sh = 0.0f;
        #pragma unroll
        for (int i = 0; i < KNOTS; i++) {
            lw[i] = expf(lw[i] - mw); sw += lw[i];
            lh[i] = expf(lh[i] - mh); sh += lh[i];
        }
        const float iw = (2.0f*BOUNDF) / sw, ih = (2.0f*BOUNDF) / sh;
        #pragma unroll
        for (int i = 0; i < KNOTS; i++) { lw[i] *= iw; lh[i] *= ih; }

        const float xv = xs[r*XD + d];
        const bool oob = (xv <= -BOUNDF) || (xv >= BOUNDF);
        const float xm = oob ? -BOUNDF : xv;

        float cumx = -BOUNDF, cumy = -BOUNDF;
        float xkb = 0.0f, ykb = 0.0f, wk = 1.0f, hk = 1.0f;
        int idx = 0; bool found = false;
        #pragma unroll
        for (int i = 0; i < KNOTS; i++) {
            float nx = cumx + lw[i];
            if (!found && (xm < nx || i == KNOTS-1)) {
                found = true; idx = i; xkb = cumx; ykb = cumy; wk = lw[i]; hk = lh[i];
            }
            cumx = nx; cumy += lh[i];
        }

        const float db = (idx == 0)        ? 1.0f : softplus_f(p[(2*KNOTS + idx - 1)*S1]);
        const float d1 = (idx == KNOTS-1)  ? 1.0f : softplus_f(p[(2*KNOTS + idx)*S1]);

        const float sk   = hk / wk;
        float relx = (xm - xkb) / wk;
        relx = fminf(fmaxf(relx, 0.0f), 1.0f);
        const float omr  = 1.0f - relx;
        const float r1v  = relx * omr;
        const float den  = sk + (d1 + db - 2.0f*sk) * r1v;
        const float num  = hk * (sk*relx*relx + db*r1v);
        float yv = ykb + num / den;
        float ld = 2.0f*logf(sk)
                 + logf(d1*relx*relx + 2.0f*sk*r1v + db*omr*omr)
                 - 2.0f*logf(den);
        if (oob) { yv = xv; ld = 0.0f; }

        ldsh[tid] = ld;
        ysh[r*XD + d] = yv;
    } else if (tid < 256) {
        // threads 192..255 copy through the upper dims for rows 0..63
        const int r = tid - 192;
        ysh[r*XD + 3] = xs[r*XD + 3];
        ysh[r*XD + 4] = xs[r*XD + 4];
        ysh[r*XD + 5] = xs[r*XD + 5];
    }
    __syncthreads();

    // ---- coalesced output ----
    for (int i = tid; i < nrows*XD; i += NTH)
        y_out[(size_t)base*XD + i] = ysh[i];
    if (tid < nrows)
        ld_out[base + tid] = ldsh[tid] + ldsh[64 + tid] + ldsh[128 + tid];
}

extern "C" void kernel_launch(void* const* d_in, const int* in_sizes, int n_in,
                              void* d_out, int out_size) {
    const float* x  = (const float*)d_in[0];
    const float* c  = (const float*)d_in[1];
    const float* W1 = (const float*)d_in[2];
    const float* b1 = (const float*)d_in[3];
    const float* W2 = (const float*)d_in[4];
    const float* b2 = (const float*)d_in[5];
    const float* W3 = (const float*)d_in[6];
    const float* b3 = (const float*)d_in[7];

    const int N = in_sizes[0] / XD;
    float* y    = (float*)d_out;
    float* ldet = y + (size_t)N * XD;

    cudaFuncSetAttribute(nsc_kernel, cudaFuncAttributeMaxDynamicSharedMemorySize, SMEM_BYTES);

    const int grid = (N + TM - 1) / TM;
    nsc_kernel<<<grid, NTH, SMEM_BYTES>>>(x, c, W1, b1, W2, b2, W3, b3, y, ldet, N);
}